// round 17
// baseline (speedup 1.0000x reference)
#include <cuda_runtime.h>
#include <cuda_fp16.h>
#include <math.h>
#include <stddef.h>
#include <stdint.h>

#define BATCH 4
#define CIN 64
#define COUT 64
#define LSEQ 131072
#define KW 9
#define PADW 4
#define TILE 128
#define JW 136 /* padded rows of xht */
#define NTHREADS 128
#define TPB_L (LSEQ / TILE)    /* 1024 */
#define NTILES (BATCH * TPB_L) /* 4096 */

/* SMEM (bytes), per CTA (3 CTAs/SM) */
#define SM_XT 0                          /* 17408 */
#define SM_C (SM_XT + JW * 128)          /* +1632 */
#define SM_W (SM_C + 3 * JW * 4)         /* +4608 */
#define SM_BIAS (SM_W + KW * TILE * 4)   /* +256 */
#define SM_ST (SM_BIAS + 256)            /* stats [16][128] f32 = 8192 */
#define SM_TOTAL (SM_ST + 16 * NTHREADS * 4) /* = 32096 */

static __device__ double g_sum[COUT];
static __device__ double g_sumsq[COUT];
static __device__ float g_scale[COUT];
static __device__ float g_shift[COUT];
/* baked fp16 B fragments, nt-paired: uint4 index ((kk*4+ks)*4+np)*32+lane */
static __device__ __align__(16) uint4 g_bfrag[KW * 4 * 4 * 32]; /* 73728 B */
/* conv scratch in fragment-native order:
   uint2 index = tile*2048 + wid*512 + (mt*4+nt)*32 + lane */
static __device__ __align__(16) __half g_scr[(size_t)BATCH * COUT * LSEQ]; /* 67 MB */

__device__ __forceinline__ uint32_t smem_u32(const void* p) {
    uint32_t a;
    asm("{ .reg .u64 t; cvta.to.shared.u64 t, %1; cvt.u32.u64 %0, t; }" : "=r"(a) : "l"(p));
    return a;
}
/* pack two f32 -> f16x2: lo half = 'even', hi half = 'odd' */
__device__ __forceinline__ uint32_t pack_f16x2(float even, float odd) {
    uint32_t r;
    asm("cvt.rn.f16x2.f32 %0, %1, %2;" : "=r"(r) : "f"(odd), "f"(even));
    return r;
}
__device__ __forceinline__ uint32_t hmul2(uint32_t a, uint32_t b) {
    uint32_t r;
    asm("mul.rn.f16x2 %0, %1, %2;" : "=r"(r) : "r"(a), "r"(b));
    return r;
}
__device__ __forceinline__ void ldsm_x4(uint32_t* r, uint32_t addr) {
    asm volatile("ldmatrix.sync.aligned.m8n8.x4.shared.b16 {%0,%1,%2,%3}, [%4];"
                 : "=r"(r[0]), "=r"(r[1]), "=r"(r[2]), "=r"(r[3])
                 : "r"(addr));
}
__device__ __forceinline__ void mma_f16(float* d, uint32_t a0, uint32_t a1, uint32_t a2,
                                        uint32_t a3, uint32_t b0, uint32_t b1) {
    asm volatile(
        "mma.sync.aligned.m16n8k16.row.col.f32.f16.f16.f32 "
        "{%0,%1,%2,%3}, {%4,%5,%6,%7}, {%8,%9}, {%0,%1,%2,%3};"
        : "+f"(d[0]), "+f"(d[1]), "+f"(d[2]), "+f"(d[3])
        : "r"(a0), "r"(a1), "r"(a2), "r"(a3), "r"(b0), "r"(b1));
}

/* Bake W into the global fp16 B-fragment table (pure function of W). */
__global__ void bake_kernel(const float* __restrict__ W) {
    for (int i = threadIdx.x; i < KW * 4 * 4 * 32; i += blockDim.x) {
        int kk = i >> 9;
        int r = i & 511;
        int ks = r >> 7;
        int r2 = r & 127;
        int np = r2 >> 5;
        int li = r2 & 31;
        int c = ks * 16 + 2 * (li & 3);
        int o0 = 2 * np * 8 + (li >> 2);
        const float* wp0 = W + (size_t)(o0 * CIN + c) * KW + kk;
        const float* wp1 = wp0 + (size_t)8 * CIN * KW;
        uint4 f;
        f.x = pack_f16x2(wp0[0], wp0[KW]);
        f.y = pack_f16x2(wp0[8 * KW], wp0[9 * KW]);
        f.z = pack_f16x2(wp1[0], wp1[KW]);
        f.w = pack_f16x2(wp1[8 * KW], wp1[9 * KW]);
        g_bfrag[i] = f;
    }
}

__global__ __launch_bounds__(NTHREADS, 3) void conv_mma_kernel(
    const float* __restrict__ x, const float* __restrict__ coords,
    const float* __restrict__ bias) {
    extern __shared__ char smem[];
    float* csh = (float*)(smem + SM_C);
    uint32_t* wsh2 = (uint32_t*)(smem + SM_W);
    float* bsh = (float*)(smem + SM_BIAS);
    float* stsh = (float*)(smem + SM_ST);
    const uint32_t sxt = smem_u32(smem + SM_XT);

    const int tid = threadIdx.x;
    const int wid = tid >> 5; /* 0..3 */
    const int lane = tid & 31;
    const int t = lane & 3;
    const int g = lane >> 2;
    const int mrowg = wid & 1;  /* 64 L rows per warp */
    const int ncolg = wid >> 1; /* 32 Couts per warp */
    const int le0 = mrowg * 64;
    const int rr = lane & 15;        /* ldmatrix row offset */
    const int ee = (lane >> 4) << 2; /* +4 words when lane>=16 */
    const int i4 = lane >> 3;        /* staging: c sub-row 0..3 */
    const int q = lane & 7;          /* staging: j quad selector */
    const int gridn = gridDim.x;

    for (int i = tid; i < COUT; i += NTHREADS) bsh[i] = bias[i];
#pragma unroll
    for (int j = 0; j < 16; j++) stsh[j * NTHREADS + tid] = 0.f;
    __syncthreads();

    /* prefetch register state (tile "next") */
    float4 pa[8], pb[8];
    float cr0, cr1, cr2, cr3;
    float he[2], ho[2];

/* ---- LDG a batch of 4 x-float4s for tile (bn, l0n) into dst[] at it-range base ---- */
#define LDG_X4(dst, itbase, xbn)                                                             \
    {                                                                                        \
        _Pragma("unroll") for (int i = 0; i < 4; i++) {                                      \
            int it = (itbase) + i;                                                           \
            (dst)[((itbase) & 4) + i] = *(const float4*)((xbn) +                             \
                (size_t)(16 * wid + 4 * (it & 3) + i4) * LSEQ + 32 * (it >> 2));             \
        }                                                                                    \
    }

/* ---- LDG coords + halo for tile (bn, l0n) ---- */
#define LDG_CH(bn, l0n)                                                                      \
    {                                                                                        \
        const float* cb = coords + (size_t)(bn)*3 * LSEQ;                                    \
        int i0 = tid, i1 = tid + 128, i2 = tid + 256, i3 = tid + 384;                        \
        int d0 = i0 / JW, j0 = i0 - d0 * JW, l0c = (l0n)-PADW + j0;                          \
        int d1 = i1 / JW, j1 = i1 - d1 * JW, l1c = (l0n)-PADW + j1;                          \
        int d2 = i2 / JW, j2 = i2 - d2 * JW, l2c = (l0n)-PADW + j2;                          \
        cr0 = (l0c >= 0 && l0c < LSEQ) ? cb[(size_t)d0 * LSEQ + l0c] : 0.0f;                 \
        cr1 = (l1c >= 0 && l1c < LSEQ) ? cb[(size_t)d1 * LSEQ + l1c] : 0.0f;                 \
        cr2 = (l2c >= 0 && l2c < LSEQ) ? cb[(size_t)d2 * LSEQ + l2c] : 0.0f;                 \
        cr3 = 0.0f;                                                                         \
        if (i3 < 3 * JW) {                                                                  \
            int j3 = i3 - 2 * JW;                                                           \
            int l3c = (l0n)-PADW + j3;                                                      \
            cr3 = (l3c >= 0 && l3c < LSEQ) ? cb[(size_t)2 * LSEQ + l3c] : 0.0f;             \
        }                                                                                   \
        _Pragma("unroll") for (int e = 0; e < 2; e++) {                                     \
            int ei = tid + e * 128;                                                         \
            int c2 = ei & 31;                                                               \
            int hs = ei >> 5;                                                               \
            int hj = (hs < 4) ? hs : 128 + hs;                                              \
            int l = (l0n)-PADW + hj;                                                        \
            const float* xr = x + (size_t)(bn)*CIN * LSEQ + (size_t)(2 * c2) * LSEQ;        \
            he[e] = (l >= 0 && l < LSEQ) ? xr[l] : 0.0f;                                    \
            ho[e] = (l >= 0 && l < LSEQ) ? xr[LSEQ + l] : 0.0f;                             \
        }                                                                                   \
    }

/* ---- transpose + STS the prefetched tile (pa/pb + coords + halo) ---- */
#define STS_TILE()                                                                           \
    {                                                                                        \
        _Pragma("unroll") for (int it = 0; it < 16; it++) {                                  \
            float4 v = (it < 8) ? pa[it] : pb[it - 8];                                       \
            if (i4 & 1) { float tmp = v.x; v.x = v.y; v.y = tmp; tmp = v.z; v.z = v.w; v.w = tmp; } \
            v.y = __shfl_xor_sync(0xffffffffu, v.y, 8);                                      \
            v.w = __shfl_xor_sync(0xffffffffu, v.w, 8);                                      \
            if (i4 & 1) { float tmp = v.x; v.x = v.y; v.y = tmp; tmp = v.z; v.z = v.w; v.w = tmp; } \
            if (i4 & 2) { float tmp = v.x; v.x = v.z; v.z = tmp; tmp = v.y; v.y = v.w; v.w = tmp; } \
            v.z = __shfl_xor_sync(0xffffffffu, v.z, 16);                                     \
            v.w = __shfl_xor_sync(0xffffffffu, v.w, 16);                                     \
            if (i4 & 2) { float tmp = v.x; v.x = v.z; v.z = tmp; tmp = v.y; v.y = v.w; v.w = tmp; } \
            int j = PADW + 32 * (it >> 2) + 4 * q + i4;                                      \
            int c2 = 8 * wid + 2 * (it & 3);                                                 \
            uint32_t h0 = pack_f16x2(v.x, v.y);                                              \
            uint32_t h1 = pack_f16x2(v.z, v.w);                                              \
            uint32_t word = (uint32_t)j * 32 + (((uint32_t)c2) ^ (((uint32_t)(j & 7)) << 2)); \
            asm volatile("st.shared.v2.b32 [%0], {%1, %2};" ::"r"(sxt + word * 4), "r"(h0),  \
                         "r"(h1)                                                             \
                         : "memory");                                                        \
        }                                                                                    \
        _Pragma("unroll") for (int e = 0; e < 2; e++) {                                      \
            int ei = tid + e * 128;                                                          \
            int c2 = ei & 31;                                                                \
            int hs = ei >> 5;                                                                \
            int hj = (hs < 4) ? hs : 128 + hs;                                               \
            uint32_t h = pack_f16x2(he[e], ho[e]);                                           \
            uint32_t word = (uint32_t)hj * 32 + (((uint32_t)c2) ^ (((uint32_t)(hj & 7)) << 2)); \
            asm volatile("st.shared.b32 [%0], %1;" ::"r"(sxt + word * 4), "r"(h) : "memory"); \
        }                                                                                    \
        csh[tid] = cr0;                                                                      \
        csh[tid + 128] = cr1;                                                                \
        csh[tid + 256] = cr2;                                                                \
        if (tid + 384 < 3 * JW) csh[tid + 384] = cr3;                                        \
    }

/* ---- gaussian weights from staged coords ---- */
#define WEIGHTS()                                                                            \
    for (int i = tid; i < KW * TILE; i += NTHREADS) {                                        \
        int k = i >> 7;                                                                      \
        int lc = i & (TILE - 1);                                                             \
        float d0 = csh[lc + k] - csh[lc + PADW];                                             \
        float d1 = csh[JW + lc + k] - csh[JW + lc + PADW];                                   \
        float d2 = csh[2 * JW + lc + k] - csh[2 * JW + lc + PADW];                           \
        float w = __expf(-0.5f * (d0 * d0 + d1 * d1 + d2 * d2));                             \
        wsh2[i] = pack_f16x2(w, w);                                                          \
    }

/* ---- mainloop over kk range; B fragments streamed from L1-resident global ---- */
#define MAINLOOP(KK0, KK1)                                                                   \
    _Pragma("unroll 1") for (int kk = (KK0); kk < (KK1); kk++) {                             \
        uint32_t wh[4][2];                                                                   \
        uint32_t rowa[4], mxor[4];                                                           \
        _Pragma("unroll") for (int mt = 0; mt < 4; mt++) {                                   \
            wh[mt][0] = wsh2[kk * TILE + le0 + mt * 16 + g];                                 \
            wh[mt][1] = wsh2[kk * TILE + le0 + mt * 16 + g + 8];                             \
            int jj = le0 + mt * 16 + kk + rr;                                                \
            rowa[mt] = sxt + (uint32_t)jj * 128;                                             \
            mxor[mt] = ((uint32_t)(jj & 7)) << 2;                                            \
        }                                                                                    \
        _Pragma("unroll") for (int ks = 0; ks < 4; ks++) {                                   \
            const uint4* fbq = g_bfrag + (size_t)(((kk * 4 + ks) * 4 + ncolg * 2) * 32 + lane); \
            uint4 q0 = __ldg(fbq);                                                           \
            uint4 q1 = __ldg(fbq + 32);                                                      \
            const uint32_t koff = ((uint32_t)(8 * ks) + (uint32_t)ee);                       \
            uint32_t acur[4], anext[4];                                                      \
            ldsm_x4(acur, rowa[0] + ((koff ^ mxor[0]) << 2));                                \
            _Pragma("unroll") for (int mt = 0; mt < 4; mt++) {                               \
                if (mt < 3) ldsm_x4(anext, rowa[mt + 1] + ((koff ^ mxor[mt + 1]) << 2));     \
                uint32_t a0 = hmul2(acur[0], wh[mt][0]);                                     \
                uint32_t a1 = hmul2(acur[1], wh[mt][1]);                                     \
                uint32_t a2 = hmul2(acur[2], wh[mt][0]);                                     \
                uint32_t a3 = hmul2(acur[3], wh[mt][1]);                                     \
                mma_f16(acc[mt][0], a0, a1, a2, a3, q0.x, q0.y);                             \
                mma_f16(acc[mt][1], a0, a1, a2, a3, q0.z, q0.w);                             \
                mma_f16(acc[mt][2], a0, a1, a2, a3, q1.x, q1.y);                             \
                mma_f16(acc[mt][3], a0, a1, a2, a3, q1.z, q1.w);                             \
                if (mt < 3) {                                                                \
                    acur[0] = anext[0];                                                      \
                    acur[1] = anext[1];                                                      \
                    acur[2] = anext[2];                                                      \
                    acur[3] = anext[3];                                                      \
                }                                                                            \
            }                                                                                \
        }                                                                                    \
    }

    /* ---- prologue: stage the first tile (latency exposed once) ---- */
    const int tt0 = blockIdx.x;
    if (tt0 < NTILES) {
        const int b = tt0 >> 10;
        const int l0 = (tt0 & (TPB_L - 1)) * TILE;
        const float* xb = x + (size_t)b * CIN * LSEQ + l0 + 4 * q;
        LDG_X4(pa, 0, xb);
        LDG_X4(pa, 4, xb);
        LDG_X4(pb, 8, xb);
        LDG_X4(pb, 12, xb);
        LDG_CH(b, l0);
        STS_TILE();
        __syncthreads();
        WEIGHTS();
        __syncthreads();
    }

    for (int tt = tt0; tt < NTILES; tt += gridn) {
        const int tn = tt + gridn;
        const bool have = tn < NTILES;
        const int bn = tn >> 10;
        const int l0n = (tn & (TPB_L - 1)) * TILE;
        const float* xbn = x + (size_t)bn * CIN * LSEQ + l0n + 4 * q;

        /* issue next tile's loads; they complete under the mainloop */
        if (have) {
            LDG_X4(pa, 0, xbn);
            LDG_X4(pa, 4, xbn);
            LDG_CH(bn, l0n);
        }

        float acc[4][4][4];
#pragma unroll
        for (int mt = 0; mt < 4; mt++)
#pragma unroll
            for (int nt = 0; nt < 4; nt++)
#pragma unroll
                for (int j = 0; j < 4; j++) acc[mt][nt][j] = 0.f;

        MAINLOOP(0, 4);
        if (have) {
            LDG_X4(pb, 8, xbn);
            LDG_X4(pb, 12, xbn);
        }
        MAINLOOP(4, KW);

        /* epilogue: +bias, stats (smem), fragment-native coalesced scratch store */
        uint2* scrt = (uint2*)g_scr + ((size_t)tt * 2048 + (size_t)wid * 512 + lane);
#pragma unroll
        for (int mt = 0; mt < 4; mt++) {
#pragma unroll
            for (int nt = 0; nt < 4; nt++) {
                int o = ncolg * 32 + nt * 8 + t * 2;
                float b0 = bsh[o];
                float b1 = bsh[o + 1];
                float v0 = acc[mt][nt][0] + b0;
                float v1 = acc[mt][nt][1] + b1;
                float v2 = acc[mt][nt][2] + b0;
                float v3 = acc[mt][nt][3] + b1;
                uint2 hv;
                hv.x = pack_f16x2(v0, v1);
                hv.y = pack_f16x2(v2, v3);
                scrt[(mt * 4 + nt) * 32] = hv;
                float* st = stsh + (nt * 4) * NTHREADS + tid;
                st[0] += v0 + v2;
                st[NTHREADS] += v1 + v3;
                st[2 * NTHREADS] += v0 * v0 + v2 * v2;
                st[3 * NTHREADS] += v1 * v1 + v3 * v3;
            }
        }

        __syncthreads(); /* all reads of xht/wsh2 for tile tt done */
        if (have) {
            STS_TILE();
            __syncthreads();
            WEIGHTS();
            __syncthreads();
        }
    }

    /* flush stats: read smem partials, reduce over lanes sharing t, atomics */
#pragma unroll
    for (int nt = 0; nt < 4; nt++)
#pragma unroll
        for (int j = 0; j < 2; j++) {
            float a = stsh[(nt * 4 + j) * NTHREADS + tid];
            float q2 = stsh[(nt * 4 + 2 + j) * NTHREADS + tid];
#pragma unroll
            for (int off = 16; off >= 4; off >>= 1) {
                a += __shfl_xor_sync(0xffffffffu, a, off);
                q2 += __shfl_xor_sync(0xffffffffu, q2, off);
            }
            if (g == 0) {
                int o = ncolg * 32 + nt * 8 + t * 2 + j;
                atomicAdd(&g_sum[o], (double)a);
                atomicAdd(&g_sumsq[o], (double)q2);
            }
        }
}

/* Computes per-channel scale/shift, then resets accumulators for the next
   (graph-replayed) run. Statics are zero-initialized at module load. */
__global__ void stats_kernel(const float* __restrict__ gamma, const float* __restrict__ beta) {
    int o = threadIdx.x;
    if (o < COUT) {
        double N = (double)BATCH * (double)LSEQ;
        double mean = g_sum[o] / N;
        double var = g_sumsq[o] / N - mean * mean;
        double rstd = 1.0 / sqrt(var + 1e-5);
        float sc = gamma[o] * (float)rstd;
        g_scale[o] = sc;
        g_shift[o] = beta[o] - (float)mean * sc;
        g_sum[o] = 0.0;
        g_sumsq[o] = 0.0;
    }
}

/* Reads fragment-native scratch, decodes (tile, wid, mt, nt, lane) -> (b, o, le),
   applies BN+ReLU, writes out[b][o][l]. Writes are 32B-sector aligned. */
__global__ void norm_kernel(float* __restrict__ out) {
    const size_t total = (size_t)NTILES * 2048; /* uint2 elements */
    size_t stride = (size_t)gridDim.x * blockDim.x;
    const uint2* scr2 = (const uint2*)g_scr;
    for (size_t i = (size_t)blockIdx.x * blockDim.x + threadIdx.x; i < total; i += stride) {
        uint2 hv = scr2[i];
        int tile = (int)(i >> 11);
        int r = (int)i & 2047;
        int lane = r & 31;
        int nt = (r >> 5) & 3;
        int mt = (r >> 7) & 3;
        int wd = r >> 9;
        int b = tile >> 10;
        int l0 = (tile & 1023) << 7;
        int le = (wd & 1) * 64 + mt * 16 + (lane >> 2);
        int o = (wd >> 1) * 32 + nt * 8 + (lane & 3) * 2;
        float2 f01 = __half22float2(*(const __half2*)&hv.x); /* (o,le), (o+1,le)   */
        float2 f23 = __half22float2(*(const __half2*)&hv.y); /* (o,le+8),(o+1,le+8)*/
        float sc0 = g_scale[o], sh0 = g_shift[o];
        float sc1 = g_scale[o + 1], sh1 = g_shift[o + 1];
        float* ob = out + ((size_t)b * COUT + o) * LSEQ + l0 + le;
        ob[0] = fmaxf(fmaf(f01.x, sc0, sh0), 0.0f);
        ob[LSEQ] = fmaxf(fmaf(f01.y, sc1, sh1), 0.0f);
        ob[8] = fmaxf(fmaf(f23.x, sc0, sh0), 0.0f);
        ob[LSEQ + 8] = fmaxf(fmaf(f23.y, sc1, sh1), 0.0f);
    }
}

extern "C" void kernel_launch(void* const* d_in, const int* in_sizes, int n_in, void* d_out,
                              int out_size) {
    const float* x = (const float*)d_in[0];       // [4,64,131072]
    const float* coords = (const float*)d_in[1];  // [4,3,131072]
    const float* W = (const float*)d_in[2];       // [64,64,9]
    const float* bias = (const float*)d_in[3];    // [64]
    const float* gamma = (const float*)d_in[4];   // [64]
    const float* beta = (const float*)d_in[5];    // [64]
    float* out = (float*)d_out;

    cudaFuncSetAttribute(conv_mma_kernel, cudaFuncAttributeMaxDynamicSharedMemorySize, SM_TOTAL);
    int sms = 148;
    cudaDeviceGetAttribute(&sms, cudaDevAttrMultiProcessorCount, 0);

    bake_kernel<<<1, 128>>>(W);
    conv_mma_kernel<<<3 * sms, NTHREADS, SM_TOTAL>>>(x, coords, bias);
    stats_kernel<<<1, 64>>>(gamma, beta);
    norm_kernel<<<8192, 256>>>(out);
}